// round 7
// baseline (speedup 1.0000x reference)
#include <cuda_runtime.h>
#include <math.h>

namespace {

constexpr int B_ = 8;
constexpr int T_ = 256;
constexpr int D_ = 12;
constexpr int H_ = 4;

// Scratch: per-token qkv [q0..11 k0..11 v0..11], and attention head output o[12]
__device__ float g_qkv[B_ * T_ * 36];
__device__ float g_o[B_ * T_ * 12];

// ======================= K1: QKV projection =============================
// one thread per token; 32 blocks x 64 threads
__global__ __launch_bounds__(64, 1) void qkv_kernel(
    const float* __restrict__ x,
    const float* __restrict__ Wi, const float* __restrict__ bi)
{
    __shared__ float sW[432 + 36];
    const int tid = threadIdx.x;
    for (int i = tid; i < 432; i += 64) sW[i] = Wi[i];
    if (tid < 36) sW[432 + tid] = bi[tid];
    __syncthreads();

    const int tok = blockIdx.x * 64 + tid;   // 0..2047
    const float* xg = x + (size_t)tok * D_;
    float xr[D_];
    #pragma unroll
    for (int i = 0; i < D_; i++) xr[i] = xg[i];

    float o[36];
    #pragma unroll
    for (int r = 0; r < 36; r++) {
        float a = sW[432 + r];
        #pragma unroll
        for (int c = 0; c < D_; c++) a = fmaf(sW[r * D_ + c], xr[c], a);
        o[r] = a;
    }
    float4* dst = (float4*)(g_qkv + (size_t)tok * 36);
    #pragma unroll
    for (int i = 0; i < 9; i++)
        dst[i] = make_float4(o[4*i], o[4*i+1], o[4*i+2], o[4*i+3]);
}

// ======================= K2: attention ==================================
// 128 blocks x 128 threads. Block = (batch, 16-query chunk).
// Thread = (query qi 0..15, head h 0..3, key-half 0..1).
__global__ __launch_bounds__(128, 1) void attn_kernel(
    const int* __restrict__ mask)
{
    __shared__ float sK[T_][D_];
    __shared__ float sV[T_][D_];
    __shared__ int   sM[T_];

    const int b  = blockIdx.x >> 4;          // /16
    const int qc = blockIdx.x & 15;
    const int tid = threadIdx.x;

    // stage K/V for the whole batch: 2 tokens per thread
    {
        const int t0 = tid * 2;
        #pragma unroll
        for (int u = 0; u < 2; u++) {
            const int tok = t0 + u;
            const float4* src = (const float4*)(g_qkv + (size_t)(b * T_ + tok) * 36 + 12);
            float4 k0 = src[0], k1 = src[1], k2 = src[2];
            float4 v0 = src[3], v1 = src[4], v2 = src[5];
            *(float4*)&sK[tok][0] = k0; *(float4*)&sK[tok][4] = k1; *(float4*)&sK[tok][8] = k2;
            *(float4*)&sV[tok][0] = v0; *(float4*)&sV[tok][4] = v1; *(float4*)&sV[tok][8] = v2;
            sM[tok] = mask[b * T_ + tok];
        }
    }

    const int qi   = tid >> 3;
    const int sub  = tid & 7;
    const int h    = sub >> 1;
    const int half = sub & 1;
    const int tq   = qc * 16 + qi;

    // this thread's query slice (3 floats of head h)
    float q0, q1, q2;
    {
        const float* qsrc = g_qkv + (size_t)(b * T_ + tq) * 36 + h * 3;
        q0 = qsrc[0]; q1 = qsrc[1]; q2 = qsrc[2];
    }
    __syncthreads();

    const float scale = 0.57735026918962576451f;  // 1/sqrt(3)
    float l = 0.f, a0 = 0.f, a1 = 0.f, a2 = 0.f;
    const int k0 = half * 128;

    #pragma unroll 4
    for (int kk = k0; kk < k0 + 128; kk++) {
        const float* kr = &sK[kk][h * 3];
        const float* vr = &sV[kk][h * 3];
        float s = (q0 * kr[0] + q1 * kr[1] + q2 * kr[2]) * scale;
        s = (sM[kk] != 0) ? -1e30f : s;
        const float p = __expf(s);
        l  += p;
        a0 = fmaf(p, vr[0], a0);
        a1 = fmaf(p, vr[1], a1);
        a2 = fmaf(p, vr[2], a2);
    }

    // combine the two key-halves (adjacent lanes)
    l  += __shfl_xor_sync(0xffffffffu, l,  1);
    a0 += __shfl_xor_sync(0xffffffffu, a0, 1);
    a1 += __shfl_xor_sync(0xffffffffu, a1, 1);
    a2 += __shfl_xor_sync(0xffffffffu, a2, 1);

    if (half == 0) {
        const float inv = 1.0f / l;
        float* dst = g_o + (size_t)(b * T_ + tq) * 12 + h * 3;
        dst[0] = a0 * inv;
        dst[1] = a1 * inv;
        dst[2] = a2 * inv;
    }
}

// ======================= K3: epilogue ===================================
// one thread per token; 64 blocks x 32 threads
// sW layout: Wo 0 | bo 144 | thA 156 | W1 168 | b1 312 | cThF 324 |
//            W2 336 | b2 480 | g1 492 | be1 504 | g2 516 | be2 528  (540)
__global__ __launch_bounds__(32, 1) void epi_kernel(
    const float* __restrict__ x,
    const float* __restrict__ Wo, const float* __restrict__ bo,
    const float* __restrict__ thA,
    const float* __restrict__ W1, const float* __restrict__ b1,
    const float* __restrict__ thF,
    const float* __restrict__ W2, const float* __restrict__ b2,
    const float* __restrict__ g1, const float* __restrict__ be1,
    const float* __restrict__ g2, const float* __restrict__ be2,
    float* __restrict__ out)
{
    __shared__ float sW[540];
    const int tid = threadIdx.x;
    for (int i = tid; i < 144; i += 32) {
        sW[i]       = Wo[i];
        sW[168 + i] = W1[i];
        sW[336 + i] = W2[i];
    }
    if (tid < 12) {
        sW[144 + tid] = bo[tid];
        sW[156 + tid] = thA[tid];
        sW[312 + tid] = b1[tid];
        sW[324 + tid] = cosf(thF[tid]);
        sW[480 + tid] = b2[tid];
        sW[492 + tid] = g1[tid];
        sW[504 + tid] = be1[tid];
        sW[516 + tid] = g2[tid];
        sW[528 + tid] = be2[tid];
    }
    __syncthreads();

    const int tok = blockIdx.x * 32 + tid;   // 0..2047
    float o[D_], xr[D_];
    {
        const float* osrc = g_o + (size_t)tok * 12;
        const float* xsrc = x + (size_t)tok * D_;
        #pragma unroll
        for (int i = 0; i < D_; i++) { o[i] = osrc[i]; xr[i] = xsrc[i]; }
    }

    // out projection
    float ac[D_];
    #pragma unroll
    for (int r = 0; r < D_; r++) {
        float a = sW[144 + r];
        #pragma unroll
        for (int c = 0; c < D_; c++) a = fmaf(sW[r * D_ + c], o[c], a);
        ac[r] = a;
    }

    // quantum attention layer (analytic):
    // z_w = cos(ac_w + thA_w); out_w = prod_{0..w} z (w>=1); out_0 = prod_{1..11} z
    float z[D_];
    #pragma unroll
    for (int w = 0; w < D_; w++) z[w] = cosf(ac[w] + sW[156 + w]);
    float aq[D_];
    {
        float run = z[0];
        #pragma unroll
        for (int w = 1; w < D_; w++) { run *= z[w]; aq[w] = run; }
        float r2 = z[1];
        #pragma unroll
        for (int w = 2; w < D_; w++) r2 *= z[w];
        aq[0] = r2;
    }

    // LayerNorm 1
    float x1[D_];
    {
        float h1[D_];
        float m = 0.f;
        #pragma unroll
        for (int w = 0; w < D_; w++) { h1[w] = xr[w] + aq[w]; m += h1[w]; }
        m *= (1.0f / D_);
        float v = 0.f;
        #pragma unroll
        for (int w = 0; w < D_; w++) { const float d = h1[w] - m; v = fmaf(d, d, v); }
        v *= (1.0f / D_);
        const float rstd = rsqrtf(v + 1e-5f);
        #pragma unroll
        for (int w = 0; w < D_; w++)
            x1[w] = (h1[w] - m) * rstd * sW[492 + w] + sW[504 + w];
    }

    // quantum FFN: lin1 -> analytic RY(th)RX(a) circuit -> lin2 -> relu
    float zf[D_];
    #pragma unroll
    for (int r = 0; r < D_; r++) {
        float a = sW[312 + r];
        #pragma unroll
        for (int c = 0; c < D_; c++) a = fmaf(sW[168 + r * D_ + c], x1[c], a);
        zf[r] = sW[324 + r] * cosf(a);
    }
    float fq[D_];
    {
        float run = zf[0];
        #pragma unroll
        for (int w = 1; w < D_; w++) { run *= zf[w]; fq[w] = run; }
        float r2 = zf[1];
        #pragma unroll
        for (int w = 2; w < D_; w++) r2 *= zf[w];
        fq[0] = r2;
    }
    float y[D_];
    #pragma unroll
    for (int r = 0; r < D_; r++) {
        float a = sW[480 + r];
        #pragma unroll
        for (int c = 0; c < D_; c++) a = fmaf(sW[336 + r * D_ + c], fq[c], a);
        y[r] = fmaxf(a, 0.f);
    }

    // LayerNorm 2 + store
    {
        float h2[D_];
        float m = 0.f;
        #pragma unroll
        for (int w = 0; w < D_; w++) { h2[w] = x1[w] + y[w]; m += h2[w]; }
        m *= (1.0f / D_);
        float v = 0.f;
        #pragma unroll
        for (int w = 0; w < D_; w++) { const float d = h2[w] - m; v = fmaf(d, d, v); }
        v *= (1.0f / D_);
        const float rstd = rsqrtf(v + 1e-5f);
        float res[D_];
        #pragma unroll
        for (int w = 0; w < D_; w++)
            res[w] = (h2[w] - m) * rstd * sW[516 + w] + sW[528 + w];
        float4* orow = (float4*)(out + (size_t)tok * D_);
        orow[0] = make_float4(res[0], res[1], res[2],  res[3]);
        orow[1] = make_float4(res[4], res[5], res[6],  res[7]);
        orow[2] = make_float4(res[8], res[9], res[10], res[11]);
    }
}

}  // namespace

extern "C" void kernel_launch(void* const* d_in, const int* in_sizes, int n_in,
                              void* d_out, int out_size) {
    (void)in_sizes; (void)n_in; (void)out_size;
    const float* x   = (const float*)d_in[0];
    const float* Wi  = (const float*)d_in[1];
    const float* bi  = (const float*)d_in[2];
    const float* Wo  = (const float*)d_in[3];
    const float* bo  = (const float*)d_in[4];
    const float* thA = (const float*)d_in[5];
    const float* W1  = (const float*)d_in[6];
    const float* b1  = (const float*)d_in[7];
    const float* thF = (const float*)d_in[8];
    const float* W2  = (const float*)d_in[9];
    const float* b2  = (const float*)d_in[10];
    const float* g1  = (const float*)d_in[11];
    const float* be1 = (const float*)d_in[12];
    const float* g2  = (const float*)d_in[13];
    const float* be2 = (const float*)d_in[14];
    const int*   msk = (const int*)d_in[15];
    float* out = (float*)d_out;

    qkv_kernel<<<32, 64>>>(x, Wi, bi);
    attn_kernel<<<128, 128>>>(msk);
    epi_kernel<<<64, 32>>>(x, Wo, bo, thA, W1, b1, thF, W2, b2,
                           g1, be1, g2, be2, out);
}

// round 9
// speedup vs baseline: 1.1233x; 1.1233x over previous
#include <cuda_runtime.h>
#include <math.h>

namespace {

constexpr int B_ = 8;
constexpr int T_ = 256;
constexpr int D_ = 12;
constexpr int QCH = 16;               // queries per block
constexpr int NTHR = 128;

// sE layout (floats):
//  Wo 0 | bo 144 | thA 156 | W1 168 | b1 312 | cThF 324 |
//  W2 336 | b2 480 | g1 492 | be1 504 | g2 516 | be2 528   (540)

__global__ __launch_bounds__(NTHR, 1) void fused_kernel(
    const float* __restrict__ x,
    const float* __restrict__ Wi, const float* __restrict__ bi,
    const float* __restrict__ Wo, const float* __restrict__ bo,
    const float* __restrict__ thA,
    const float* __restrict__ W1, const float* __restrict__ b1,
    const float* __restrict__ thF,
    const float* __restrict__ W2, const float* __restrict__ b2,
    const float* __restrict__ g1, const float* __restrict__ be1,
    const float* __restrict__ g2, const float* __restrict__ be2,
    const int* __restrict__ mask,
    float* __restrict__ out)
{
    __shared__ float sK[T_][D_];
    __shared__ float sV[T_][D_];
    __shared__ int   sM[T_];
    __shared__ float sWi[432 + 36];   // Wi | bi
    __shared__ float sE[540];         // epilogue weights
    __shared__ float sO[QCH][D_];     // attention head outputs

    const int b   = blockIdx.x >> 4;
    const int qc  = blockIdx.x & 15;
    const int tid = threadIdx.x;

    // ---- stage phase (all scalar, R7-style) -------------------------------
    for (int i = tid; i < 432; i += NTHR) sWi[i] = Wi[i];
    if (tid < 36) sWi[432 + tid] = bi[tid];
    for (int i = tid; i < 144; i += NTHR) {
        sE[i]       = Wo[i];
        sE[168 + i] = W1[i];
        sE[336 + i] = W2[i];
    }
    if (tid < 12) {
        sE[144 + tid] = bo[tid];
        sE[156 + tid] = thA[tid];
        sE[312 + tid] = b1[tid];
        sE[324 + tid] = cosf(thF[tid]);
        sE[480 + tid] = b2[tid];
        sE[492 + tid] = g1[tid];
        sE[504 + tid] = be1[tid];
        sE[516 + tid] = g2[tid];
        sE[528 + tid] = be2[tid];
    }
    sM[tid]        = mask[b * T_ + tid];
    sM[tid + NTHR] = mask[b * T_ + tid + NTHR];
    __syncthreads();

    // ---- K/V for the whole batch from GLOBAL x (2 tokens per thread) ------
    #pragma unroll
    for (int u = 0; u < 2; u++) {
        const int tok = tid * 2 + u;
        const float* xg = x + (size_t)(b * T_ + tok) * D_;
        float xr[D_];
        #pragma unroll
        for (int i = 0; i < D_; i++) xr[i] = xg[i];
        #pragma unroll
        for (int r = 0; r < D_; r++) {
            float ak = sWi[432 + 12 + r];
            float av = sWi[432 + 24 + r];
            #pragma unroll
            for (int c = 0; c < D_; c++) {
                ak = fmaf(sWi[(12 + r) * D_ + c], xr[c], ak);
                av = fmaf(sWi[(24 + r) * D_ + c], xr[c], av);
            }
            sK[tok][r] = ak;
            sV[tok][r] = av;
        }
    }

    // ---- this thread's query slice: (qi, head h, key-half) ----------------
    const int qi   = tid >> 3;
    const int sub  = tid & 7;
    const int h    = sub >> 1;
    const int half = sub & 1;
    const int tq   = qc * QCH + qi;

    float q0, q1, q2;
    {
        const float* xg = x + (size_t)(b * T_ + tq) * D_;
        float xq[D_];
        #pragma unroll
        for (int i = 0; i < D_; i++) xq[i] = xg[i];
        const int r0 = h * 3;
        float a0 = sWi[432 + r0], a1 = sWi[432 + r0 + 1], a2 = sWi[432 + r0 + 2];
        #pragma unroll
        for (int c = 0; c < D_; c++) {
            a0 = fmaf(sWi[(r0    ) * D_ + c], xq[c], a0);
            a1 = fmaf(sWi[(r0 + 1) * D_ + c], xq[c], a1);
            a2 = fmaf(sWi[(r0 + 2) * D_ + c], xq[c], a2);
        }
        q0 = a0; q1 = a1; q2 = a2;
    }
    __syncthreads();

    // ---- attention: 128 keys/thread, one-pass max-free softmax (R7 loop) --
    const float scale = 0.57735026918962576451f;  // 1/sqrt(3)
    float l = 0.f, a0 = 0.f, a1 = 0.f, a2 = 0.f;
    const int kbase = half * 128;

    #pragma unroll 4
    for (int kk = kbase; kk < kbase + 128; kk++) {
        const float* kr = &sK[kk][h * 3];
        const float* vr = &sV[kk][h * 3];
        float s = (q0 * kr[0] + q1 * kr[1] + q2 * kr[2]) * scale;
        s = (sM[kk] != 0) ? -1e30f : s;
        const float p = __expf(s);
        l  += p;
        a0 = fmaf(p, vr[0], a0);
        a1 = fmaf(p, vr[1], a1);
        a2 = fmaf(p, vr[2], a2);
    }
    l  += __shfl_xor_sync(0xffffffffu, l,  1);
    a0 += __shfl_xor_sync(0xffffffffu, a0, 1);
    a1 += __shfl_xor_sync(0xffffffffu, a1, 1);
    a2 += __shfl_xor_sync(0xffffffffu, a2, 1);

    if (half == 0) {
        const float inv = 1.0f / l;
        sO[qi][h * 3]     = a0 * inv;
        sO[qi][h * 3 + 1] = a1 * inv;
        sO[qi][h * 3 + 2] = a2 * inv;
    }
    __syncthreads();

    // ---- epilogue: threads 0..15, one token each (verbatim R7 math) -------
    if (tid < QCH) {
        const int tqe = qc * QCH + tid;
        float o[D_], xr[D_];
        {
            const float* xg = x + (size_t)(b * T_ + tqe) * D_;
            #pragma unroll
            for (int i = 0; i < D_; i++) { o[i] = sO[tid][i]; xr[i] = xg[i]; }
        }

        // out projection
        float ac[D_];
        #pragma unroll
        for (int r = 0; r < D_; r++) {
            float a = sE[144 + r];
            #pragma unroll
            for (int c = 0; c < D_; c++) a = fmaf(sE[r * D_ + c], o[c], a);
            ac[r] = a;
        }

        // quantum attention layer (analytic CNOT-ring Z expectations)
        float z[D_];
        #pragma unroll
        for (int w = 0; w < D_; w++) z[w] = cosf(ac[w] + sE[156 + w]);
        float aq[D_];
        {
            float run = z[0];
            #pragma unroll
            for (int w = 1; w < D_; w++) { run *= z[w]; aq[w] = run; }
            float r2 = z[1];
            #pragma unroll
            for (int w = 2; w < D_; w++) r2 *= z[w];
            aq[0] = r2;
        }

        // LayerNorm 1
        float x1[D_];
        {
            float h1[D_];
            float m = 0.f;
            #pragma unroll
            for (int w = 0; w < D_; w++) { h1[w] = xr[w] + aq[w]; m += h1[w]; }
            m *= (1.0f / D_);
            float v = 0.f;
            #pragma unroll
            for (int w = 0; w < D_; w++) { const float d = h1[w] - m; v = fmaf(d, d, v); }
            v *= (1.0f / D_);
            const float rstd = rsqrtf(v + 1e-5f);
            #pragma unroll
            for (int w = 0; w < D_; w++)
                x1[w] = (h1[w] - m) * rstd * sE[492 + w] + sE[504 + w];
        }

        // quantum FFN: lin1 -> analytic RY(th)RX(a) -> lin2 -> relu
        float zf[D_];
        #pragma unroll
        for (int r = 0; r < D_; r++) {
            float a = sE[312 + r];
            #pragma unroll
            for (int c = 0; c < D_; c++) a = fmaf(sE[168 + r * D_ + c], x1[c], a);
            zf[r] = sE[324 + r] * cosf(a);
        }
        float fq[D_];
        {
            float run = zf[0];
            #pragma unroll
            for (int w = 1; w < D_; w++) { run *= zf[w]; fq[w] = run; }
            float r2 = zf[1];
            #pragma unroll
            for (int w = 2; w < D_; w++) r2 *= zf[w];
            fq[0] = r2;
        }
        float y[D_];
        #pragma unroll
        for (int r = 0; r < D_; r++) {
            float a = sE[480 + r];
            #pragma unroll
            for (int c = 0; c < D_; c++) a = fmaf(sE[336 + r * D_ + c], fq[c], a);
            y[r] = fmaxf(a, 0.f);
        }

        // LayerNorm 2 + store
        {
            float h2[D_];
            float m = 0.f;
            #pragma unroll
            for (int w = 0; w < D_; w++) { h2[w] = x1[w] + y[w]; m += h2[w]; }
            m *= (1.0f / D_);
            float v = 0.f;
            #pragma unroll
            for (int w = 0; w < D_; w++) { const float d = h2[w] - m; v = fmaf(d, d, v); }
            v *= (1.0f / D_);
            const float rstd = rsqrtf(v + 1e-5f);
            float res[D_];
            #pragma unroll
            for (int w = 0; w < D_; w++)
                res[w] = (h2[w] - m) * rstd * sE[516 + w] + sE[528 + w];
            float4* orow = (float4*)(out + (size_t)(b * T_ + tqe) * D_);
            orow[0] = make_float4(res[0], res[1], res[2],  res[3]);
            orow[1] = make_float4(res[4], res[5], res[6],  res[7]);
            orow[2] = make_float4(res[8], res[9], res[10], res[11]);
        }
    }
}

}  // namespace

extern "C" void kernel_launch(void* const* d_in, const int* in_sizes, int n_in,
                              void* d_out, int out_size) {
    (void)in_sizes; (void)n_in; (void)out_size;
    fused_kernel<<<B_ * 16, NTHR>>>(
        (const float*)d_in[0],   // x
        (const float*)d_in[1],   // in_proj_w
        (const float*)d_in[2],   // in_proj_b
        (const float*)d_in[3],   // out_proj_w
        (const float*)d_in[4],   // out_proj_b
        (const float*)d_in[5],   // attn_theta
        (const float*)d_in[6],   // lin1_w
        (const float*)d_in[7],   // lin1_b
        (const float*)d_in[8],   // ffn_theta
        (const float*)d_in[9],   // lin2_w
        (const float*)d_in[10],  // lin2_b
        (const float*)d_in[11],  // ln1_g
        (const float*)d_in[12],  // ln1_b
        (const float*)d_in[13],  // ln2_g
        (const float*)d_in[14],  // ln2_b
        (const int*)d_in[15],    // mask
        (float*)d_out);
}